// round 1
// baseline (speedup 1.0000x reference)
#include <cuda_runtime.h>
#include <math.h>

#define NN 50000
#define NE 800000
#define DIN 32
#define DD 128
#define NL 3
#define NG 64

#define BM 64
#define LDA 260   // As row pitch (257 padded to mult of 4)
#define LDH 132   // Hs row pitch
#define SMEM_FLOATS (BM*LDA + BM*LDH + 16*DD)
#define SMEM_BYTES (SMEM_FLOATS*4)

__device__ float g_agg[(size_t)NN * DD];
__device__ float g_upd[(size_t)NN * DD];
__device__ int   g_counts[NG];

__device__ __forceinline__ float gelu_f(float x) {
    return 0.5f * x * (1.0f + erff(x * 0.7071067811865475f));
}

__device__ __forceinline__ void ffma2(unsigned long long &c, unsigned long long a, unsigned long long b) {
    asm("fma.rn.f32x2 %0, %1, %2, %0;" : "+l"(c) : "l"(a), "l"(b));
}
__device__ __forceinline__ unsigned long long pack2(float x) {
    unsigned long long r;
    asm("mov.b64 %0, {%1, %1};" : "=l"(r) : "f"(x));
    return r;
}
__device__ __forceinline__ float2 unpack2(unsigned long long v) {
    float2 f;
    asm("mov.b64 {%0, %1}, %2;" : "=f"(f.x), "=f"(f.y) : "l"(v));
    return f;
}

// MODE 0: edge MLP (gather hidden[src],hidden[dst],ew -> 2 GEMMs -> atomic scatter to g_agg)
// MODE 1: node update MLP ([hidden|agg] -> 2 GEMMs -> store g_upd)
template<int MODE>
__global__ void __launch_bounds__(128, 2) fused_mlp_kernel(
    const float* __restrict__ hidden,
    const int* __restrict__ src, const int* __restrict__ dst,
    const float* __restrict__ ew,
    const float* __restrict__ W1, const float* __restrict__ b1,
    const float* __restrict__ W2, const float* __restrict__ b2,
    int M)
{
    extern __shared__ float sm[];
    float* As = sm;                // [BM][LDA]
    float* Hs = As + BM * LDA;     // [BM][LDH]
    float* Wb = Hs + BM * LDH;     // [16][DD]

    const int tid = threadIdx.x;
    const int tx = tid & 15;       // 0..15  -> output cols tx*8..+7
    const int ty = tid >> 4;       // 0..7   -> rows ty*8..+7
    const int m0 = blockIdx.x * BM;

    // ---------------- gather A tile (row-major) ----------------
    {
        const int r = tid >> 1;    // 0..63
        const int h = tid & 1;     // which 64-float half
        const int row = m0 + r;
        float4* a0 = (float4*)&As[r * LDA + h * 64];
        float4* a1 = (float4*)&As[r * LDA + 128 + h * 64];
        if (row < M) {
            const float* p0;
            const float* p1;
            if (MODE == 0) {
                p0 = hidden + (size_t)src[row] * DD + h * 64;
                p1 = hidden + (size_t)dst[row] * DD + h * 64;
            } else {
                p0 = hidden + (size_t)row * DD + h * 64;
                p1 = g_agg  + (size_t)row * DD + h * 64;
            }
            #pragma unroll
            for (int i = 0; i < 16; i++) a0[i] = ((const float4*)p0)[i];
            #pragma unroll
            for (int i = 0; i < 16; i++) a1[i] = ((const float4*)p1)[i];
            if (MODE == 0 && h == 0) As[r * LDA + 256] = ew[row];
        } else {
            float4 z = make_float4(0.f, 0.f, 0.f, 0.f);
            #pragma unroll
            for (int i = 0; i < 16; i++) a0[i] = z;
            #pragma unroll
            for (int i = 0; i < 16; i++) a1[i] = z;
            if (MODE == 0 && h == 0) As[r * LDA + 256] = 0.f;
        }
    }

    const int wrow = tid >> 3;           // 0..15
    const int wcol = (tid & 7) << 4;     // 0,16,...,112

    unsigned long long c[8][4];
    float4 wreg[4];

    // shared-A GEMM with W streamed via smem (register-prefetch double buffer)
    auto gemm = [&](const float* A, int lda, const float* W, int ktiles) {
        #pragma unroll
        for (int i = 0; i < 8; i++) {
            c[i][0] = 0ull; c[i][1] = 0ull; c[i][2] = 0ull; c[i][3] = 0ull;
        }
        {
            const float4* p = (const float4*)(W + (size_t)wrow * DD + wcol);
            wreg[0] = p[0]; wreg[1] = p[1]; wreg[2] = p[2]; wreg[3] = p[3];
        }
        for (int kt = 0; kt < ktiles; ++kt) {
            __syncthreads();
            {
                float4* wp = (float4*)&Wb[wrow * DD + wcol];
                wp[0] = wreg[0]; wp[1] = wreg[1]; wp[2] = wreg[2]; wp[3] = wreg[3];
            }
            __syncthreads();
            if (kt + 1 < ktiles) {
                const float4* p = (const float4*)(W + (size_t)((kt + 1) * 16 + wrow) * DD + wcol);
                wreg[0] = p[0]; wreg[1] = p[1]; wreg[2] = p[2]; wreg[3] = p[3];
            }
            #pragma unroll
            for (int kq = 0; kq < 4; ++kq) {
                float av[8][4];
                #pragma unroll
                for (int i = 0; i < 8; i++)
                    *(float4*)av[i] = *(const float4*)&A[(size_t)(ty * 8 + i) * lda + kt * 16 + kq * 4];
                #pragma unroll
                for (int kk = 0; kk < 4; ++kk) {
                    const ulonglong2* wr = (const ulonglong2*)&Wb[(kq * 4 + kk) * DD + tx * 8];
                    ulonglong2 w01 = wr[0];
                    ulonglong2 w23 = wr[1];
                    #pragma unroll
                    for (int i = 0; i < 8; i++) {
                        unsigned long long ap = pack2(av[i][kk]);
                        ffma2(c[i][0], ap, w01.x);
                        ffma2(c[i][1], ap, w01.y);
                        ffma2(c[i][2], ap, w23.x);
                        ffma2(c[i][3], ap, w23.y);
                    }
                }
            }
        }
    };

    // ---------------- GEMM1: A[BM,K1] x W1[K1,128] ----------------
    gemm(As, LDA, W1, 16);   // k = 0..255
    if (MODE == 0) {
        // tail k = 256 (edge weight column)
        const ulonglong2* tp = (const ulonglong2*)(W1 + (size_t)256 * DD + tx * 8);
        ulonglong2 w01 = tp[0], w23 = tp[1];
        #pragma unroll
        for (int i = 0; i < 8; i++) {
            unsigned long long ap = pack2(As[(size_t)(ty * 8 + i) * LDA + 256]);
            ffma2(c[i][0], ap, w01.x);
            ffma2(c[i][1], ap, w01.y);
            ffma2(c[i][2], ap, w23.x);
            ffma2(c[i][3], ap, w23.y);
        }
    }

    // epilogue 1: +b1, gelu, write Hs (row-major)
    {
        float4 b1a = ((const float4*)(b1 + tx * 8))[0];
        float4 b1b = ((const float4*)(b1 + tx * 8))[1];
        #pragma unroll
        for (int i = 0; i < 8; i++) {
            float2 v0 = unpack2(c[i][0]);
            float2 v1 = unpack2(c[i][1]);
            float2 v2 = unpack2(c[i][2]);
            float2 v3 = unpack2(c[i][3]);
            float4 o0, o1;
            o0.x = gelu_f(v0.x + b1a.x); o0.y = gelu_f(v0.y + b1a.y);
            o0.z = gelu_f(v1.x + b1a.z); o0.w = gelu_f(v1.y + b1a.w);
            o1.x = gelu_f(v2.x + b1b.x); o1.y = gelu_f(v2.y + b1b.y);
            o1.z = gelu_f(v3.x + b1b.z); o1.w = gelu_f(v3.y + b1b.w);
            float4* hp = (float4*)&Hs[(size_t)(ty * 8 + i) * LDH + tx * 8];
            hp[0] = o0; hp[1] = o1;
        }
    }

    // ---------------- GEMM2: Hs[BM,128] x W2[128,128] ----------------
    gemm(Hs, LDH, W2, 8);

    // epilogue 2: +b2, scatter/store
    {
        float4 b2a = ((const float4*)(b2 + tx * 8))[0];
        float4 b2b = ((const float4*)(b2 + tx * 8))[1];
        #pragma unroll
        for (int i = 0; i < 8; i++) {
            int row = m0 + ty * 8 + i;
            if (row < M) {
                float2 v0 = unpack2(c[i][0]);
                float2 v1 = unpack2(c[i][1]);
                float2 v2 = unpack2(c[i][2]);
                float2 v3 = unpack2(c[i][3]);
                float o[8] = { v0.x + b2a.x, v0.y + b2a.y, v1.x + b2a.z, v1.y + b2a.w,
                               v2.x + b2b.x, v2.y + b2b.y, v3.x + b2b.z, v3.y + b2b.w };
                if (MODE == 0) {
                    float* base = g_agg + (size_t)dst[row] * DD + tx * 8;
                    #pragma unroll
                    for (int j = 0; j < 8; j++) atomicAdd(base + j, o[j]);
                } else {
                    float* base = g_upd + (size_t)row * DD + tx * 8;
                    ((float4*)base)[0] = make_float4(o[0], o[1], o[2], o[3]);
                    ((float4*)base)[1] = make_float4(o[4], o[5], o[6], o[7]);
                }
            }
        }
    }
}

__global__ void input_proj_kernel(const float* __restrict__ x, const float* __restrict__ W,
                                  const float* __restrict__ b, float* __restrict__ hidden)
{
    int gid = blockIdx.x * blockDim.x + threadIdx.x;
    if (gid >= NN * 32) return;
    int node = gid >> 5;
    int c4 = (gid & 31) << 2;
    const float* xr = x + (size_t)node * DIN;
    float4 acc = *(const float4*)(b + c4);
    #pragma unroll
    for (int k = 0; k < DIN; k++) {
        float xv = xr[k];
        float4 w = *(const float4*)(W + (size_t)k * DD + c4);
        acc.x += xv * w.x; acc.y += xv * w.y; acc.z += xv * w.z; acc.w += xv * w.w;
    }
    float4 o = make_float4(gelu_f(acc.x), gelu_f(acc.y), gelu_f(acc.z), gelu_f(acc.w));
    *(float4*)(hidden + (size_t)node * DD + c4) = o;
}

__global__ void ln_kernel(float* __restrict__ hidden, const float* __restrict__ gamma,
                          const float* __restrict__ beta)
{
    int gw = (blockIdx.x * blockDim.x + threadIdx.x) >> 5;
    if (gw >= NN) return;
    int lane = threadIdx.x & 31;
    float4 h = ((const float4*)(hidden + (size_t)gw * DD))[lane];
    float4 u = ((const float4*)(g_upd + (size_t)gw * DD))[lane];
    float x0 = h.x + u.x, x1 = h.y + u.y, x2 = h.z + u.z, x3 = h.w + u.w;
    float s = x0 + x1 + x2 + x3;
    #pragma unroll
    for (int o = 16; o > 0; o >>= 1) s += __shfl_xor_sync(0xffffffffu, s, o);
    float mu = s * (1.0f / 128.0f);
    float d0 = x0 - mu, d1 = x1 - mu, d2 = x2 - mu, d3 = x3 - mu;
    float v = d0 * d0 + d1 * d1 + d2 * d2 + d3 * d3;
    #pragma unroll
    for (int o = 16; o > 0; o >>= 1) v += __shfl_xor_sync(0xffffffffu, v, o);
    float r = rsqrtf(v * (1.0f / 128.0f) + 1e-5f);
    float4 g = ((const float4*)gamma)[lane];
    float4 bb = ((const float4*)beta)[lane];
    float4 o4 = make_float4(d0 * r * g.x + bb.x, d1 * r * g.y + bb.y,
                            d2 * r * g.z + bb.z, d3 * r * g.w + bb.w);
    ((float4*)(hidden + (size_t)gw * DD))[lane] = o4;
}

__global__ void zero_agg_kernel()
{
    int gid = blockIdx.x * blockDim.x + threadIdx.x;
    if (gid < NN * DD / 4) ((float4*)g_agg)[gid] = make_float4(0.f, 0.f, 0.f, 0.f);
}

__global__ void zero_pool_kernel(float* __restrict__ out)
{
    int gid = blockIdx.x * blockDim.x + threadIdx.x;
    if (gid < NG * DD) out[(size_t)NN * DD + gid] = 0.f;
    if (gid < NG) g_counts[gid] = 0;
}

__global__ void pool_accum_kernel(const float* __restrict__ hidden, const int* __restrict__ batch,
                                  float* __restrict__ out)
{
    int gid = blockIdx.x * blockDim.x + threadIdx.x;
    if (gid >= NN * 32) return;
    int node = gid >> 5;
    int c4 = (gid & 31) << 2;
    int g = batch[node];
    float4 h = *(const float4*)(hidden + (size_t)node * DD + c4);
    float* base = out + (size_t)NN * DD + (size_t)g * DD + c4;
    atomicAdd(base + 0, h.x);
    atomicAdd(base + 1, h.y);
    atomicAdd(base + 2, h.z);
    atomicAdd(base + 3, h.w);
    if ((gid & 31) == 0) atomicAdd(&g_counts[g], 1);
}

__global__ void pool_div_kernel(float* __restrict__ out)
{
    int gid = blockIdx.x * blockDim.x + threadIdx.x;
    if (gid >= NG * DD) return;
    int g = gid >> 7;
    int cnt = g_counts[g];
    float cden = (float)(cnt > 1 ? cnt : 1);
    out[(size_t)NN * DD + gid] /= cden;
}

extern "C" void kernel_launch(void* const* d_in, const int* in_sizes, int n_in,
                              void* d_out, int out_size)
{
    const float* node_features = (const float*)d_in[0];
    const int*   edge_index    = (const int*)d_in[1];
    const float* edge_weight   = (const float*)d_in[2];
    const int*   batch_index   = (const int*)d_in[3];
    const float* W_in  = (const float*)d_in[5];
    const float* b_in  = (const float*)d_in[6];
    const float* eW1   = (const float*)d_in[7];
    const float* eb1   = (const float*)d_in[8];
    const float* eW2   = (const float*)d_in[9];
    const float* eb2   = (const float*)d_in[10];
    const float* uW1   = (const float*)d_in[11];
    const float* ub1   = (const float*)d_in[12];
    const float* uW2   = (const float*)d_in[13];
    const float* ub2   = (const float*)d_in[14];
    const float* gamma = (const float*)d_in[15];
    const float* beta  = (const float*)d_in[16];
    float* out = (float*)d_out;

    const int* src = edge_index;
    const int* dst = edge_index + NE;

    cudaFuncSetAttribute(fused_mlp_kernel<0>, cudaFuncAttributeMaxDynamicSharedMemorySize, SMEM_BYTES);
    cudaFuncSetAttribute(fused_mlp_kernel<1>, cudaFuncAttributeMaxDynamicSharedMemorySize, SMEM_BYTES);

    zero_pool_kernel<<<(NG * DD + 255) / 256, 256>>>(out);
    input_proj_kernel<<<(NN * 32 + 255) / 256, 256>>>(node_features, W_in, b_in, out);

    for (int l = 0; l < NL; ++l) {
        zero_agg_kernel<<<(NN * DD / 4 + 255) / 256, 256>>>();
        fused_mlp_kernel<0><<<(NE + BM - 1) / BM, 128, SMEM_BYTES>>>(
            out, src, dst, edge_weight,
            eW1 + (size_t)l * 257 * DD, eb1 + (size_t)l * DD,
            eW2 + (size_t)l * DD * DD,  eb2 + (size_t)l * DD, NE);
        fused_mlp_kernel<1><<<(NN + BM - 1) / BM, 128, SMEM_BYTES>>>(
            out, (const int*)0, (const int*)0, (const float*)0,
            uW1 + (size_t)l * 256 * DD, ub1 + (size_t)l * DD,
            uW2 + (size_t)l * DD * DD,  ub2 + (size_t)l * DD, NN);
        ln_kernel<<<(NN * 32 + 255) / 256, 256>>>(out, gamma + (size_t)l * DD, beta + (size_t)l * DD);
    }

    pool_accum_kernel<<<(NN * 32 + 255) / 256, 256>>>(out, batch_index, out);
    pool_div_kernel<<<(NG * DD + 255) / 256, 256>>>(out);
}

// round 2
// speedup vs baseline: 1.2644x; 1.2644x over previous
#include <cuda_runtime.h>
#include <math.h>

#define NN 50000
#define NE 800000
#define DIN 32
#define DD 128
#define NL 3
#define NG 64

#define BM 64
#define LDA 260                 // As row pitch in floats (257 padded)
#define KT 8                    // k-rows per W stage tile
#define WBUF (KT*DD)            // 1024 floats per W buffer
#define SMEM_FLOATS (BM*LDA + 2*WBUF)
#define SMEM_BYTES (SMEM_FLOATS*4)   // 74752 bytes -> 3 CTAs/SM

__device__ float g_agg[(size_t)NN * DD];
__device__ float g_upd[(size_t)NN * DD];
__device__ int   g_counts[NG];

__device__ __forceinline__ float gelu_f(float x) {
    return 0.5f * x * (1.0f + erff(x * 0.7071067811865475f));
}

__device__ __forceinline__ void ffma2(unsigned long long &c, unsigned long long a, unsigned long long b) {
    asm("fma.rn.f32x2 %0, %1, %2, %0;" : "+l"(c) : "l"(a), "l"(b));
}
__device__ __forceinline__ unsigned long long pack2(float x) {
    unsigned long long r;
    asm("mov.b64 %0, {%1, %1};" : "=l"(r) : "f"(x));
    return r;
}
__device__ __forceinline__ float2 unpack2(unsigned long long v) {
    float2 f;
    asm("mov.b64 {%0, %1}, %2;" : "=f"(f.x), "=f"(f.y) : "l"(v));
    return f;
}

__device__ __forceinline__ void cp16(float* s, const float* g) {
    unsigned sa = (unsigned)__cvta_generic_to_shared(s);
    asm volatile("cp.async.ca.shared.global [%0], [%1], 16;" :: "r"(sa), "l"(g));
}
__device__ __forceinline__ void cp4(float* s, const float* g) {
    unsigned sa = (unsigned)__cvta_generic_to_shared(s);
    asm volatile("cp.async.ca.shared.global [%0], [%1], 4;" :: "r"(sa), "l"(g));
}
#define CP_COMMIT() asm volatile("cp.async.commit_group;")
#define CP_WAIT0()  asm volatile("cp.async.wait_group 0;")

__device__ __forceinline__ void red_add_v4(float* p, float a, float b, float c, float d) {
    asm volatile("red.global.add.v4.f32 [%0], {%1, %2, %3, %4};"
                 :: "l"(p), "f"(a), "f"(b), "f"(c), "f"(d) : "memory");
}

// MODE 0: edge MLP (gather hidden[src],hidden[dst],ew -> 2 GEMMs -> red.v4 scatter to g_agg)
// MODE 1: node update MLP ([hidden|agg] -> 2 GEMMs -> store g_upd)
template<int MODE>
__global__ void __launch_bounds__(128, 3) fused_mlp_kernel(
    const float* __restrict__ hidden,
    const int* __restrict__ src, const int* __restrict__ dst,
    const float* __restrict__ ew,
    const float* __restrict__ W1, const float* __restrict__ b1,
    const float* __restrict__ W2, const float* __restrict__ b2,
    int M)
{
    extern __shared__ float sm[];
    float* As = sm;                 // [BM][LDA]; col 256 = ew (MODE 0). Hs aliases cols 0..127 after GEMM1.
    float* Wb = sm + BM * LDA;      // [2][KT][DD] ping-pong

    const int tid = threadIdx.x;
    const int tx = tid & 15;        // output cols tx*8..+7
    const int ty = tid >> 4;        // rows ty*8..+7
    const int m0 = blockIdx.x * BM;

    const int wrow = tid >> 4;      // 0..7 -> W stage row
    const int wcol = (tid & 15) << 3;   // 0..120 step 8

    // ---------------- gather A tile via cp.async ----------------
    {
        const int r = tid >> 1;     // 0..63
        const int h = tid & 1;      // 64-float half
        const int row = m0 + r;
        float* a0 = &As[r * LDA + h * 64];
        float* a1 = &As[r * LDA + 128 + h * 64];
        if (row < M) {
            const float* p0;
            const float* p1;
            if (MODE == 0) {
                p0 = hidden + (size_t)src[row] * DD + h * 64;
                p1 = hidden + (size_t)dst[row] * DD + h * 64;
            } else {
                p0 = hidden + (size_t)row * DD + h * 64;
                p1 = g_agg  + (size_t)row * DD + h * 64;
            }
            #pragma unroll
            for (int i = 0; i < 16; i++) cp16(a0 + i * 4, p0 + i * 4);
            #pragma unroll
            for (int i = 0; i < 16; i++) cp16(a1 + i * 4, p1 + i * 4);
            if (MODE == 0 && h == 0) cp4(&As[r * LDA + 256], ew + row);
        } else {
            float4 z = make_float4(0.f, 0.f, 0.f, 0.f);
            #pragma unroll
            for (int i = 0; i < 16; i++) ((float4*)a0)[i] = z;
            #pragma unroll
            for (int i = 0; i < 16; i++) ((float4*)a1)[i] = z;
            if (MODE == 0 && h == 0) As[r * LDA + 256] = 0.f;
        }
        CP_COMMIT();
    }

    unsigned long long c[8][4];

    // shared-A GEMM, W streamed via cp.async ping-pong (1 barrier per k-tile)
    auto gemm = [&](const float* A, const float* W, int ktiles) {
        #pragma unroll
        for (int i = 0; i < 8; i++) {
            c[i][0] = 0ull; c[i][1] = 0ull; c[i][2] = 0ull; c[i][3] = 0ull;
        }
        // preload tile 0
        cp16(&Wb[wrow * DD + wcol],     W + (size_t)wrow * DD + wcol);
        cp16(&Wb[wrow * DD + wcol + 4], W + (size_t)wrow * DD + wcol + 4);
        CP_COMMIT();
        CP_WAIT0();
        __syncthreads();
        #pragma unroll 1
        for (int kt = 0; kt < ktiles; ++kt) {
            const int buf = kt & 1;
            if (kt + 1 < ktiles) {
                const float* g = W + (size_t)((kt + 1) * KT + wrow) * DD + wcol;
                float* s = &Wb[(buf ^ 1) * WBUF + wrow * DD + wcol];
                cp16(s, g);
                cp16(s + 4, g + 4);
                CP_COMMIT();
            }
            #pragma unroll
            for (int kq = 0; kq < 2; ++kq) {
                float av[8][4];
                #pragma unroll
                for (int i = 0; i < 8; i++)
                    *(float4*)av[i] = *(const float4*)&A[(size_t)(ty * 8 + i) * LDA + kt * KT + kq * 4];
                #pragma unroll
                for (int kk = 0; kk < 4; ++kk) {
                    const ulonglong2* wr = (const ulonglong2*)&Wb[buf * WBUF + (kq * 4 + kk) * DD + tx * 8];
                    ulonglong2 w01 = wr[0];
                    ulonglong2 w23 = wr[1];
                    #pragma unroll
                    for (int i = 0; i < 8; i++) {
                        unsigned long long ap = pack2(av[i][kk]);
                        ffma2(c[i][0], ap, w01.x);
                        ffma2(c[i][1], ap, w01.y);
                        ffma2(c[i][2], ap, w23.x);
                        ffma2(c[i][3], ap, w23.y);
                    }
                }
            }
            if (kt + 1 < ktiles) {
                CP_WAIT0();
                __syncthreads();
            }
        }
    };

    // ---------------- GEMM1: A[BM,K1] x W1[K1,128] ----------------
    gemm(As, W1, 32);   // k = 0..255
    if (MODE == 0) {
        // tail k = 256 (edge-weight column)
        const ulonglong2* tp = (const ulonglong2*)(W1 + (size_t)256 * DD + tx * 8);
        ulonglong2 w01 = tp[0], w23 = tp[1];
        #pragma unroll
        for (int i = 0; i < 8; i++) {
            unsigned long long ap = pack2(As[(size_t)(ty * 8 + i) * LDA + 256]);
            ffma2(c[i][0], ap, w01.x);
            ffma2(c[i][1], ap, w01.y);
            ffma2(c[i][2], ap, w23.x);
            ffma2(c[i][3], ap, w23.y);
        }
    }

    // all threads done reading A before we overwrite it with Hs
    __syncthreads();

    // epilogue 1: +b1, gelu, write Hs (aliases As cols 0..127)
    {
        float4 b1a = ((const float4*)(b1 + tx * 8))[0];
        float4 b1b = ((const float4*)(b1 + tx * 8))[1];
        #pragma unroll
        for (int i = 0; i < 8; i++) {
            float2 v0 = unpack2(c[i][0]);
            float2 v1 = unpack2(c[i][1]);
            float2 v2 = unpack2(c[i][2]);
            float2 v3 = unpack2(c[i][3]);
            float4 o0, o1;
            o0.x = gelu_f(v0.x + b1a.x); o0.y = gelu_f(v0.y + b1a.y);
            o0.z = gelu_f(v1.x + b1a.z); o0.w = gelu_f(v1.y + b1a.w);
            o1.x = gelu_f(v2.x + b1b.x); o1.y = gelu_f(v2.y + b1b.y);
            o1.z = gelu_f(v3.x + b1b.z); o1.w = gelu_f(v3.y + b1b.w);
            float4* hp = (float4*)&As[(size_t)(ty * 8 + i) * LDA + tx * 8];
            hp[0] = o0; hp[1] = o1;
        }
    }
    // gemm2's internal barrier (after W preload) publishes the Hs writes.

    // ---------------- GEMM2: Hs[BM,128] x W2[128,128] ----------------
    gemm(As, W2, 16);

    // epilogue 2: +b2, scatter/store
    {
        float4 b2a = ((const float4*)(b2 + tx * 8))[0];
        float4 b2b = ((const float4*)(b2 + tx * 8))[1];
        #pragma unroll
        for (int i = 0; i < 8; i++) {
            int row = m0 + ty * 8 + i;
            if (row < M) {
                float2 v0 = unpack2(c[i][0]);
                float2 v1 = unpack2(c[i][1]);
                float2 v2 = unpack2(c[i][2]);
                float2 v3 = unpack2(c[i][3]);
                float o0 = v0.x + b2a.x, o1 = v0.y + b2a.y, o2 = v1.x + b2a.z, o3 = v1.y + b2a.w;
                float o4 = v2.x + b2b.x, o5 = v2.y + b2b.y, o6 = v3.x + b2b.z, o7 = v3.y + b2b.w;
                if (MODE == 0) {
                    float* base = g_agg + (size_t)dst[row] * DD + tx * 8;
                    red_add_v4(base,     o0, o1, o2, o3);
                    red_add_v4(base + 4, o4, o5, o6, o7);
                } else {
                    float* base = g_upd + (size_t)row * DD + tx * 8;
                    ((float4*)base)[0] = make_float4(o0, o1, o2, o3);
                    ((float4*)base)[1] = make_float4(o4, o5, o6, o7);
                }
            }
        }
    }
}

__global__ void input_proj_kernel(const float* __restrict__ x, const float* __restrict__ W,
                                  const float* __restrict__ b, float* __restrict__ hidden)
{
    int gid = blockIdx.x * blockDim.x + threadIdx.x;
    if (gid >= NN * 32) return;
    int node = gid >> 5;
    int c4 = (gid & 31) << 2;
    const float* xr = x + (size_t)node * DIN;
    float4 acc = *(const float4*)(b + c4);
    #pragma unroll
    for (int k = 0; k < DIN; k++) {
        float xv = xr[k];
        float4 w = *(const float4*)(W + (size_t)k * DD + c4);
        acc.x += xv * w.x; acc.y += xv * w.y; acc.z += xv * w.z; acc.w += xv * w.w;
    }
    float4 o = make_float4(gelu_f(acc.x), gelu_f(acc.y), gelu_f(acc.z), gelu_f(acc.w));
    *(float4*)(hidden + (size_t)node * DD + c4) = o;
}

__global__ void ln_kernel(float* __restrict__ hidden, const float* __restrict__ gamma,
                          const float* __restrict__ beta)
{
    int gw = (blockIdx.x * blockDim.x + threadIdx.x) >> 5;
    if (gw >= NN) return;
    int lane = threadIdx.x & 31;
    float4 h = ((const float4*)(hidden + (size_t)gw * DD))[lane];
    float4 u = ((const float4*)(g_upd + (size_t)gw * DD))[lane];
    float x0 = h.x + u.x, x1 = h.y + u.y, x2 = h.z + u.z, x3 = h.w + u.w;
    float s = x0 + x1 + x2 + x3;
    #pragma unroll
    for (int o = 16; o > 0; o >>= 1) s += __shfl_xor_sync(0xffffffffu, s, o);
    float mu = s * (1.0f / 128.0f);
    float d0 = x0 - mu, d1 = x1 - mu, d2 = x2 - mu, d3 = x3 - mu;
    float v = d0 * d0 + d1 * d1 + d2 * d2 + d3 * d3;
    #pragma unroll
    for (int o = 16; o > 0; o >>= 1) v += __shfl_xor_sync(0xffffffffu, v, o);
    float r = rsqrtf(v * (1.0f / 128.0f) + 1e-5f);
    float4 g = ((const float4*)gamma)[lane];
    float4 bb = ((const float4*)beta)[lane];
    float4 o4 = make_float4(d0 * r * g.x + bb.x, d1 * r * g.y + bb.y,
                            d2 * r * g.z + bb.z, d3 * r * g.w + bb.w);
    ((float4*)(hidden + (size_t)gw * DD))[lane] = o4;
}

__global__ void zero_agg_kernel()
{
    int gid = blockIdx.x * blockDim.x + threadIdx.x;
    if (gid < NN * DD / 4) ((float4*)g_agg)[gid] = make_float4(0.f, 0.f, 0.f, 0.f);
}

__global__ void zero_pool_kernel(float* __restrict__ out)
{
    int gid = blockIdx.x * blockDim.x + threadIdx.x;
    if (gid < NG * DD) out[(size_t)NN * DD + gid] = 0.f;
    if (gid < NG) g_counts[gid] = 0;
}

__global__ void pool_accum_kernel(const float* __restrict__ hidden, const int* __restrict__ batch,
                                  float* __restrict__ out)
{
    int gid = blockIdx.x * blockDim.x + threadIdx.x;
    if (gid >= NN * 32) return;
    int node = gid >> 5;
    int c4 = (gid & 31) << 2;
    int g = batch[node];
    float4 h = *(const float4*)(hidden + (size_t)node * DD + c4);
    float* base = out + (size_t)NN * DD + (size_t)g * DD + c4;
    red_add_v4(base, h.x, h.y, h.z, h.w);
    if ((gid & 31) == 0) atomicAdd(&g_counts[g], 1);
}

__global__ void pool_div_kernel(float* __restrict__ out)
{
    int gid = blockIdx.x * blockDim.x + threadIdx.x;
    if (gid >= NG * DD) return;
    int g = gid >> 7;
    int cnt = g_counts[g];
    float cden = (float)(cnt > 1 ? cnt : 1);
    out[(size_t)NN * DD + gid] /= cden;
}

extern "C" void kernel_launch(void* const* d_in, const int* in_sizes, int n_in,
                              void* d_out, int out_size)
{
    const float* node_features = (const float*)d_in[0];
    const int*   edge_index    = (const int*)d_in[1];
    const float* edge_weight   = (const float*)d_in[2];
    const int*   batch_index   = (const int*)d_in[3];
    const float* W_in  = (const float*)d_in[5];
    const float* b_in  = (const float*)d_in[6];
    const float* eW1   = (const float*)d_in[7];
    const float* eb1   = (const float*)d_in[8];
    const float* eW2   = (const float*)d_in[9];
    const float* eb2   = (const float*)d_in[10];
    const float* uW1   = (const float*)d_in[11];
    const float* ub1   = (const float*)d_in[12];
    const float* uW2   = (const float*)d_in[13];
    const float* ub2   = (const float*)d_in[14];
    const float* gamma = (const float*)d_in[15];
    const float* beta  = (const float*)d_in[16];
    float* out = (float*)d_out;

    const int* src = edge_index;
    const int* dst = edge_index + NE;

    cudaFuncSetAttribute(fused_mlp_kernel<0>, cudaFuncAttributeMaxDynamicSharedMemorySize, SMEM_BYTES);
    cudaFuncSetAttribute(fused_mlp_kernel<1>, cudaFuncAttributeMaxDynamicSharedMemorySize, SMEM_BYTES);

    zero_pool_kernel<<<(NG * DD + 255) / 256, 256>>>(out);
    input_proj_kernel<<<(NN * 32 + 255) / 256, 256>>>(node_features, W_in, b_in, out);

    for (int l = 0; l < NL; ++l) {
        zero_agg_kernel<<<(NN * DD / 4 + 255) / 256, 256>>>();
        fused_mlp_kernel<0><<<(NE + BM - 1) / BM, 128, SMEM_BYTES>>>(
            out, src, dst, edge_weight,
            eW1 + (size_t)l * 257 * DD, eb1 + (size_t)l * DD,
            eW2 + (size_t)l * DD * DD,  eb2 + (size_t)l * DD, NE);
        fused_mlp_kernel<1><<<(NN + BM - 1) / BM, 128, SMEM_BYTES>>>(
            out, (const int*)0, (const int*)0, (const float*)0,
            uW1 + (size_t)l * 256 * DD, ub1 + (size_t)l * DD,
            uW2 + (size_t)l * DD * DD,  ub2 + (size_t)l * DD, NN);
        ln_kernel<<<(NN * 32 + 255) / 256, 256>>>(out, gamma + (size_t)l * DD, beta + (size_t)l * DD);
    }

    pool_accum_kernel<<<(NN * 32 + 255) / 256, 256>>>(out, batch_index, out);
    pool_div_kernel<<<(NG * DD + 255) / 256, 256>>>(out);
}